// round 13
// baseline (speedup 1.0000x reference)
#include <cuda_runtime.h>
#include <cstdint>

#define C_EPS     1e-12f
#define C_TOL     1e-6f
#define C_LAM     10000.0f
#define C_INVLAM  1e-4f

// One CBF-QP row, fully branchless. Identical to the last PASSING kernel (R7)
// except the s<=0 start: cubic-balance start instead of the bare deep
// asymptote. The cubic expansion is valid exactly and only where s<=0
// (root scale makes t^2 A >> N there); applying it to all b<0 rows was the
// R9/R10/R11 failure.
__device__ __forceinline__ float2 solve_row(
    float ux, float uy, float px, float py, float vx, float vy)
{
    float h  = fmaf(px, px, py * py) - 1.0f;                   // SAFE_DIST^2 = 1
    float ax = -2.0f * px, ay = -2.0f * py;
    float b  = fmaf(2.0f, h, -2.0f * fmaf(px, vx, py * vy));   // ALPHA*h - 2 p.v

    float A = fmaf(ax, ax, ay * ay);
    float p = fmaf(ax, ux, ay * uy);
    float N = fmaf(ux, ux, uy * uy);

    // ---- Case 1: clip to unit ball, test feasibility (formed vector) ----
    float s1  = fminf(1.0f, rsqrtf(fmaxf(N, C_EPS)));
    float u1x = ux * s1, u1y = uy * s1;
    bool feas1 = fmaf(ax, u1x, ay * u1y) <= b + C_TOL;

    // ---- Case 2: soft halfspace projection, ball test (formed vector) ----
    float t2  = __fdividef(C_LAM * (p - b), fmaf(C_LAM, A, 1.0f));
    float u2x = fmaf(-t2, ax, ux), u2y = fmaf(-t2, ay, uy);
    bool ok2  = (t2 >= -C_TOL) && (fmaf(u2x, u2x, u2y * u2y) <= 1.0f + C_TOL);

    // ---- Case 3 start ----
    float Ac   = fmaxf(A, 1e-30f);
    float rsA  = rsqrtf(Ac);
    float m    = Ac * rsA;                 // sqrt(A)
    float invA = rsA * rsA;                // 1/A
    float s    = fmaf(-b, b, A);           // A - b^2
    float csg  = fmaxf(fmaf(A, N, -p * p), 0.0f);   // A*N - p^2 >= 0 (C-S)
    float q    = csg * invA;               // ||u_perp||^2

    // Quadratic start (LAM->inf limit), used when s > 0 (R7 behavior).
    float rad = sqrtf(fmaxf(__fdividef(csg, s), 0.0f));
    float t_q = fmaf(-b, rad, p) * invA;

    // Cubic-balance start for s <= 0 only (there -b >= sqrt(A) > 0):
    //   t^3 - a t^2 = c,  a = (p/A)+ + LAM(-b-sqrt(A))+,  c = LAM(-b) q/(2A)
    //   t_x = a + c/(a + cbrt(c))^2  — exact in deep and crossover limits.
    float a_x = fmaxf(p * invA, 0.0f) + C_LAM * fmaxf(-b - m, 0.0f);
    float c_c = fmaxf((0.5f * C_LAM) * ((-b) * q) * invA, 0.0f);
    float cr  = exp2f(0.33333333f * __log2f(c_c));             // cbrt; 0 if c_c=0
    float den = a_x + cr;
    float t_x = a_x + __fdividef(c_c, fmaxf(den * den, 1e-30f));

    float t3 = (s > 0.0f) ? t_q : t_x;

    // Safeguard bounds on the root (R7).
    float hb = p * invA;
    if (b < 0.0f) hb = fmaxf(hb, -C_LAM * b);
    t3 = fminf(fmaxf(t3, 0.0f), hb);

    // ---- 6 safeguarded Newton steps on exact phi (R7) ----
    #pragma unroll
    for (int k = 0; k < 6; k++) {
        float nrm2 = fmaxf(fmaf(t3, fmaf(t3, A, -2.0f * p), N), C_EPS);
        float rn   = rsqrtf(nrm2);
        float nrm  = nrm2 * rn;
        float R    = fmaf(t3, C_INVLAM, b);
        float L    = fmaf(-t3, A, p);
        float f    = fmaf(-R, nrm, L);
        float df   = fmaf(R * L, rn, fmaf(-C_INVLAM, nrm, -A));
        df = (fabsf(df) > 1e-8f) ? df : -1e-8f;
        t3 = fminf(fmaxf(t3 - __fdividef(f, df), 0.0f), hb);
    }

    float nrm2 = fmaxf(fmaf(t3, fmaf(t3, A, -2.0f * p), N), C_EPS);
    float inv3 = fminf(rsqrtf(nrm2), 1.0f);                    // 1/max(nrm,1)
    float u3x  = fmaf(-t3, ax, ux) * inv3;
    float u3y  = fmaf(-t3, ay, uy) * inv3;

    float ox = feas1 ? u1x : (ok2 ? u2x : u3x);
    float oy = feas1 ? u1y : (ok2 ? u2y : u3y);
    return make_float2(ox, oy);
}

// 2 rows per thread, float4 I/O (u: 1x128b, obs: 3x128b, out: 1x128b per pair).
__global__ void __launch_bounds__(256) cbf_fused2_kernel(
    const float4* __restrict__ u4,
    const float4* __restrict__ o4,
    float4*       __restrict__ out4,
    int npair)
{
    int j = blockIdx.x * 256 + threadIdx.x;
    if (j >= npair) return;

    float4 u  = u4[j];
    float4 a0 = o4[3 * j + 0];   // row0: o0 o1 o2 o3
    float4 a1 = o4[3 * j + 1];   // row0: o4 o5 | row1: o0 o1
    float4 a2 = o4[3 * j + 2];   // row1: o2 o3 o4 o5

    float2 r0 = solve_row(u.x, u.y, a0.z, a0.w, a1.x, a1.y);
    float2 r1 = solve_row(u.z, u.w, a2.x, a2.y, a2.z, a2.w);

    out4[j] = make_float4(r0.x, r0.y, r1.x, r1.y);
}

// Scalar tail for odd n (not hit at B = 4M).
__global__ void cbf_tail_kernel(
    const float* __restrict__ u_nom,
    const float* __restrict__ obs,
    float*       __restrict__ out,
    int i)
{
    const float* o = obs + 6 * i;
    float2 r = solve_row(u_nom[2 * i], u_nom[2 * i + 1], o[2], o[3], o[4], o[5]);
    out[2 * i]     = r.x;
    out[2 * i + 1] = r.y;
}

extern "C" void kernel_launch(void* const* d_in, const int* in_sizes, int n_in,
                              void* d_out, int out_size) {
    const float* u_nom = (const float*)d_in[0];
    const float* obs   = (const float*)d_in[1];
    float* out = (float*)d_out;

    int n = in_sizes[0] / 2;
    int npair = n / 2;

    int threads = 256;
    int blocks  = (npair + threads - 1) / threads;
    cbf_fused2_kernel<<<blocks, threads>>>(
        (const float4*)u_nom, (const float4*)obs, (float4*)out, npair);

    if (n & 1)
        cbf_tail_kernel<<<1, 1>>>(u_nom, obs, out, n - 1);
}

// round 14
// speedup vs baseline: 1.1714x; 1.1714x over previous
#include <cuda_runtime.h>
#include <cstdint>

#define C_EPS     1e-12f
#define C_TOL     1e-6f
#define C_LAM     10000.0f
#define C_INVLAM  1e-4f

// One CBF-QP row, fully branchless. Identical to the passing R13 kernel
// (rel_err 1.1e-7) except Newton steps 6 -> 4: measured convergence showed
// the last two steps at the fp32 noise floor.
__device__ __forceinline__ float2 solve_row(
    float ux, float uy, float px, float py, float vx, float vy)
{
    float h  = fmaf(px, px, py * py) - 1.0f;                   // SAFE_DIST^2 = 1
    float ax = -2.0f * px, ay = -2.0f * py;
    float b  = fmaf(2.0f, h, -2.0f * fmaf(px, vx, py * vy));   // ALPHA*h - 2 p.v

    float A = fmaf(ax, ax, ay * ay);
    float p = fmaf(ax, ux, ay * uy);
    float N = fmaf(ux, ux, uy * uy);

    // ---- Case 1: clip to unit ball, test feasibility (formed vector) ----
    float s1  = fminf(1.0f, rsqrtf(fmaxf(N, C_EPS)));
    float u1x = ux * s1, u1y = uy * s1;
    bool feas1 = fmaf(ax, u1x, ay * u1y) <= b + C_TOL;

    // ---- Case 2: soft halfspace projection, ball test (formed vector) ----
    float t2  = __fdividef(C_LAM * (p - b), fmaf(C_LAM, A, 1.0f));
    float u2x = fmaf(-t2, ax, ux), u2y = fmaf(-t2, ay, uy);
    bool ok2  = (t2 >= -C_TOL) && (fmaf(u2x, u2x, u2y * u2y) <= 1.0f + C_TOL);

    // ---- Case 3 start ----
    float Ac   = fmaxf(A, 1e-30f);
    float rsA  = rsqrtf(Ac);
    float m    = Ac * rsA;                 // sqrt(A)
    float invA = rsA * rsA;                // 1/A
    float s    = fmaf(-b, b, A);           // A - b^2
    float csg  = fmaxf(fmaf(A, N, -p * p), 0.0f);   // A*N - p^2 >= 0 (C-S)
    float q    = csg * invA;               // ||u_perp||^2

    // Quadratic start (LAM->inf limit), used when s > 0.
    float rad = sqrtf(fmaxf(__fdividef(csg, s), 0.0f));
    float t_q = fmaf(-b, rad, p) * invA;

    // Cubic-balance start for s <= 0 only (there -b >= sqrt(A) > 0):
    //   t^3 - a t^2 = c,  a = (p/A)+ + LAM(-b-sqrt(A))+,  c = LAM(-b) q/(2A)
    //   t_x = a + c/(a + cbrt(c))^2  — exact in deep and crossover limits.
    float a_x = fmaxf(p * invA, 0.0f) + C_LAM * fmaxf(-b - m, 0.0f);
    float c_c = fmaxf((0.5f * C_LAM) * ((-b) * q) * invA, 0.0f);
    float cr  = exp2f(0.33333333f * __log2f(c_c));             // cbrt; 0 if c_c=0
    float den = a_x + cr;
    float t_x = a_x + __fdividef(c_c, fmaxf(den * den, 1e-30f));

    float t3 = (s > 0.0f) ? t_q : t_x;

    // Safeguard bounds on the root.
    float hb = p * invA;
    if (b < 0.0f) hb = fmaxf(hb, -C_LAM * b);
    t3 = fminf(fmaxf(t3, 0.0f), hb);

    // ---- 4 safeguarded Newton steps on exact phi ----
    #pragma unroll
    for (int k = 0; k < 4; k++) {
        float nrm2 = fmaxf(fmaf(t3, fmaf(t3, A, -2.0f * p), N), C_EPS);
        float rn   = rsqrtf(nrm2);
        float nrm  = nrm2 * rn;
        float R    = fmaf(t3, C_INVLAM, b);
        float L    = fmaf(-t3, A, p);
        float f    = fmaf(-R, nrm, L);
        float df   = fmaf(R * L, rn, fmaf(-C_INVLAM, nrm, -A));
        df = (fabsf(df) > 1e-8f) ? df : -1e-8f;
        t3 = fminf(fmaxf(t3 - __fdividef(f, df), 0.0f), hb);
    }

    float nrm2 = fmaxf(fmaf(t3, fmaf(t3, A, -2.0f * p), N), C_EPS);
    float inv3 = fminf(rsqrtf(nrm2), 1.0f);                    // 1/max(nrm,1)
    float u3x  = fmaf(-t3, ax, ux) * inv3;
    float u3y  = fmaf(-t3, ay, uy) * inv3;

    float ox = feas1 ? u1x : (ok2 ? u2x : u3x);
    float oy = feas1 ? u1y : (ok2 ? u2y : u3y);
    return make_float2(ox, oy);
}

// 2 rows per thread, float4 I/O (u: 1x128b, obs: 3x128b, out: 1x128b per pair).
__global__ void __launch_bounds__(256) cbf_fused2_kernel(
    const float4* __restrict__ u4,
    const float4* __restrict__ o4,
    float4*       __restrict__ out4,
    int npair)
{
    int j = blockIdx.x * 256 + threadIdx.x;
    if (j >= npair) return;

    float4 u  = u4[j];
    float4 a0 = o4[3 * j + 0];   // row0: o0 o1 o2 o3
    float4 a1 = o4[3 * j + 1];   // row0: o4 o5 | row1: o0 o1
    float4 a2 = o4[3 * j + 2];   // row1: o2 o3 o4 o5

    float2 r0 = solve_row(u.x, u.y, a0.z, a0.w, a1.x, a1.y);
    float2 r1 = solve_row(u.z, u.w, a2.x, a2.y, a2.z, a2.w);

    out4[j] = make_float4(r0.x, r0.y, r1.x, r1.y);
}

// Scalar tail for odd n (not hit at B = 4M).
__global__ void cbf_tail_kernel(
    const float* __restrict__ u_nom,
    const float* __restrict__ obs,
    float*       __restrict__ out,
    int i)
{
    const float* o = obs + 6 * i;
    float2 r = solve_row(u_nom[2 * i], u_nom[2 * i + 1], o[2], o[3], o[4], o[5]);
    out[2 * i]     = r.x;
    out[2 * i + 1] = r.y;
}

extern "C" void kernel_launch(void* const* d_in, const int* in_sizes, int n_in,
                              void* d_out, int out_size) {
    const float* u_nom = (const float*)d_in[0];
    const float* obs   = (const float*)d_in[1];
    float* out = (float*)d_out;

    int n = in_sizes[0] / 2;
    int npair = n / 2;

    int threads = 256;
    int blocks  = (npair + threads - 1) / threads;
    cbf_fused2_kernel<<<blocks, threads>>>(
        (const float4*)u_nom, (const float4*)obs, (float4*)out, npair);

    if (n & 1)
        cbf_tail_kernel<<<1, 1>>>(u_nom, obs, out, n - 1);
}

// round 15
// speedup vs baseline: 1.2405x; 1.0590x over previous
#include <cuda_runtime.h>
#include <cstdint>

#define C_EPS     1e-12f
#define C_TOL     1e-6f
#define C_LAM     10000.0f
#define C_INVLAM  1e-4f

// One CBF-QP row, fully branchless. Same as passing R14 except the Newton
// loop runs on the SQUARED residual F(t) = L^2 - R^2*nrm2 (pure FMA, no
// rsqrt per iteration). Spurious F-roots (L = -R*nrm) are provably outside
// [lb, hb], enforced each iterate.
__device__ __forceinline__ float2 solve_row(
    float ux, float uy, float px, float py, float vx, float vy)
{
    float h  = fmaf(px, px, py * py) - 1.0f;                   // SAFE_DIST^2 = 1
    float ax = -2.0f * px, ay = -2.0f * py;
    float b  = fmaf(2.0f, h, -2.0f * fmaf(px, vx, py * vy));   // ALPHA*h - 2 p.v

    float A = fmaf(ax, ax, ay * ay);
    float p = fmaf(ax, ux, ay * uy);
    float N = fmaf(ux, ux, uy * uy);

    // ---- Case 1: clip to unit ball, test feasibility (formed vector) ----
    float s1  = fminf(1.0f, rsqrtf(fmaxf(N, C_EPS)));
    float u1x = ux * s1, u1y = uy * s1;
    bool feas1 = fmaf(ax, u1x, ay * u1y) <= b + C_TOL;

    // ---- Case 2: soft halfspace projection, ball test (formed vector) ----
    float t2  = __fdividef(C_LAM * (p - b), fmaf(C_LAM, A, 1.0f));
    float u2x = fmaf(-t2, ax, ux), u2y = fmaf(-t2, ay, uy);
    bool ok2  = (t2 >= -C_TOL) && (fmaf(u2x, u2x, u2y * u2y) <= 1.0f + C_TOL);

    // ---- Case 3 start (identical to R13/R14) ----
    float Ac   = fmaxf(A, 1e-30f);
    float rsA  = rsqrtf(Ac);
    float m    = Ac * rsA;                 // sqrt(A)
    float invA = rsA * rsA;                // 1/A
    float s    = fmaf(-b, b, A);           // A - b^2
    float csg  = fmaxf(fmaf(A, N, -p * p), 0.0f);   // A*N - p^2 >= 0 (C-S)
    float q    = csg * invA;               // ||u_perp||^2

    // Quadratic start (LAM->inf limit), used when s > 0.
    // sqrt via clamped x*rsqrt(x): exact enough, no IEEE-sqrt sequence,
    // and well-defined at x=0 and x->inf (clamps keep it finite).
    float x   = fminf(fmaxf(__fdividef(csg, s), 1e-38f), 1e38f);
    float rad = x * rsqrtf(x);
    float t_q = fmaf(-b, rad, p) * invA;

    // Cubic-balance start for s <= 0 only:
    //   t^3 - a t^2 = c,  a = (p/A)+ + LAM(-b-sqrt(A))+,  c = LAM(-b) q/(2A)
    float a_x = fmaxf(p * invA, 0.0f) + C_LAM * fmaxf(-b - m, 0.0f);
    float c_c = fmaxf((0.5f * C_LAM) * ((-b) * q) * invA, 0.0f);
    float cr  = exp2f(0.33333333f * __log2f(c_c));             // cbrt; 0 if c_c=0
    float den = a_x + cr;
    float t_x = a_x + __fdividef(c_c, fmaxf(den * den, 1e-30f));

    float t3 = (s > 0.0f) ? t_q : t_x;

    // Safeguard bounds. hb as in R14. lb excludes the spurious F-root:
    // for b<0 with R(p/A) < 0, all L>0 spurious roots have t < p/A; the
    // L<0 spurious roots lie above hb in every sub-regime.
    float poA = p * invA;
    float hb  = poA;
    float lb  = 0.0f;
    if (b < 0.0f) {
        hb = fmaxf(hb, -C_LAM * b);
        if (fmaf(poA, C_INVLAM, b) < 0.0f) lb = poA;
    }
    t3 = fminf(fmaxf(t3, lb), hb);

    // ---- 4 Newton steps on F(t) = L^2 - R^2*nrm2 (sqrt-free) ----
    // F' /2 = L*(R^2 - A) - (1/LAM)*R*nrm2
    #pragma unroll
    for (int k = 0; k < 4; k++) {
        float nrm2 = fmaxf(fmaf(t3, fmaf(t3, A, -2.0f * p), N), C_EPS);
        float L    = fmaf(-t3, A, p);
        float R    = fmaf(t3, C_INVLAM, b);
        float Rn   = R * nrm2;
        float s2   = fmaf(R, R, -A);
        float F    = fmaf(L, L, -R * Rn);
        float Fh   = fmaf(L, s2, -C_INVLAM * Rn);              // F'/2
        Fh = (fabsf(Fh) > 1e-12f) ? Fh : -1e-12f;
        t3 = t3 - __fdividef(0.5f * F, Fh);
        t3 = fminf(fmaxf(t3, lb), hb);
    }

    float nrm2 = fmaxf(fmaf(t3, fmaf(t3, A, -2.0f * p), N), C_EPS);
    float inv3 = fminf(rsqrtf(nrm2), 1.0f);                    // 1/max(nrm,1)
    float u3x  = fmaf(-t3, ax, ux) * inv3;
    float u3y  = fmaf(-t3, ay, uy) * inv3;

    float ox = feas1 ? u1x : (ok2 ? u2x : u3x);
    float oy = feas1 ? u1y : (ok2 ? u2y : u3y);
    return make_float2(ox, oy);
}

// 2 rows per thread, float4 I/O (u: 1x128b, obs: 3x128b, out: 1x128b per pair).
__global__ void __launch_bounds__(256) cbf_fused2_kernel(
    const float4* __restrict__ u4,
    const float4* __restrict__ o4,
    float4*       __restrict__ out4,
    int npair)
{
    int j = blockIdx.x * 256 + threadIdx.x;
    if (j >= npair) return;

    float4 u  = u4[j];
    float4 a0 = o4[3 * j + 0];   // row0: o0 o1 o2 o3
    float4 a1 = o4[3 * j + 1];   // row0: o4 o5 | row1: o0 o1
    float4 a2 = o4[3 * j + 2];   // row1: o2 o3 o4 o5

    float2 r0 = solve_row(u.x, u.y, a0.z, a0.w, a1.x, a1.y);
    float2 r1 = solve_row(u.z, u.w, a2.x, a2.y, a2.z, a2.w);

    out4[j] = make_float4(r0.x, r0.y, r1.x, r1.y);
}

// Scalar tail for odd n (not hit at B = 4M).
__global__ void cbf_tail_kernel(
    const float* __restrict__ u_nom,
    const float* __restrict__ obs,
    float*       __restrict__ out,
    int i)
{
    const float* o = obs + 6 * i;
    float2 r = solve_row(u_nom[2 * i], u_nom[2 * i + 1], o[2], o[3], o[4], o[5]);
    out[2 * i]     = r.x;
    out[2 * i + 1] = r.y;
}

extern "C" void kernel_launch(void* const* d_in, const int* in_sizes, int n_in,
                              void* d_out, int out_size) {
    const float* u_nom = (const float*)d_in[0];
    const float* obs   = (const float*)d_in[1];
    float* out = (float*)d_out;

    int n = in_sizes[0] / 2;
    int npair = n / 2;

    int threads = 256;
    int blocks  = (npair + threads - 1) / threads;
    cbf_fused2_kernel<<<blocks, threads>>>(
        (const float4*)u_nom, (const float4*)obs, (float4*)out, npair);

    if (n & 1)
        cbf_tail_kernel<<<1, 1>>>(u_nom, obs, out, n - 1);
}

// round 16
// speedup vs baseline: 1.3144x; 1.0596x over previous
#include <cuda_runtime.h>
#include <cstdint>

#define C_EPS     1e-12f
#define C_TOL     1e-6f
#define C_LAM     10000.0f
#define C_INVLAM  1e-4f

// One CBF-QP row, fully branchless. Numerics identical to passing R15 except:
//  - no in-loop EPS clamp (F-Newton never divides by nrm2; t<=hb=p/A keeps
//    t^2 A <= ||u||^2, no overflow),
//  - no Fh guard (div blow-up -> inf/nan -> per-iter clamp recovers:
//    fmaxf(nan, lb) = lb),
//  - feas1 via p*s1 (no cancellation; boundary-continuous),
//  - rad via rsqrt product instead of div+sqrt.
__device__ __forceinline__ float2 solve_row(
    float ux, float uy, float px, float py, float vx, float vy)
{
    float h  = fmaf(px, px, py * py) - 1.0f;                   // SAFE_DIST^2 = 1
    float ax = -2.0f * px, ay = -2.0f * py;
    float b  = fmaf(2.0f, h, -2.0f * fmaf(px, vx, py * vy));   // ALPHA*h - 2 p.v

    float A = fmaf(ax, ax, ay * ay);
    float p = fmaf(ax, ux, ay * uy);
    float N = fmaf(ux, ux, uy * uy);

    // ---- Case 1: clip to unit ball; feasibility via p*s1 (= a.u1 up to ulp) ----
    float s1  = fminf(1.0f, rsqrtf(fmaxf(N, C_EPS)));
    float u1x = ux * s1, u1y = uy * s1;
    bool feas1 = p * s1 <= b + C_TOL;

    // ---- Case 2: soft halfspace projection, ball test on formed vector ----
    float t2  = __fdividef(C_LAM * (p - b), fmaf(C_LAM, A, 1.0f));
    float u2x = fmaf(-t2, ax, ux), u2y = fmaf(-t2, ay, uy);
    bool ok2  = (t2 >= -C_TOL) && (fmaf(u2x, u2x, u2y * u2y) <= 1.0f + C_TOL);

    // ---- Case 3 start ----
    float Ac   = fmaxf(A, 1e-30f);
    float rsA  = rsqrtf(Ac);
    float m    = Ac * rsA;                 // sqrt(A)
    float invA = rsA * rsA;                // 1/A
    float s    = fmaf(-b, b, A);           // A - b^2
    float cs   = fmaxf(fmaf(A, N, -p * p), 1e-30f);  // A*N - p^2 >= 0 (C-S)
    float q    = cs * invA;                // ||u_perp||^2

    // Quadratic start (s > 0): rad = sqrt(cs/s) = cs*rsqrt(cs)*rsqrt(s).
    // s <= 0 -> rsqrt(neg) = nan -> t_q nan, not selected.
    float rad = cs * rsqrtf(cs) * rsqrtf(s);
    float t_q = fmaf(-b, rad, p) * invA;

    // Cubic-balance start for s <= 0 only (-b >= sqrt(A) > 0 there):
    //   t^3 - a t^2 = c,  a = (p/A)+ + LAM(-b-sqrt(A))+,  c = LAM(-b) q/(2A)
    float a_x = fmaxf(p * invA, 0.0f) + C_LAM * fmaxf(-b - m, 0.0f);
    float c_c = fmaxf((0.5f * C_LAM) * ((-b) * q) * invA, 0.0f);
    float cr  = exp2f(0.33333333f * __log2f(c_c));             // cbrt; 0 if c_c=0
    float den = a_x + cr;
    float t_x = a_x + __fdividef(c_c, fmaxf(den * den, 1e-30f));

    float t3 = (s > 0.0f) ? t_q : t_x;

    // Safeguard bounds (exclude spurious F-root basins, clamp overshoot).
    float poA = p * invA;
    float hb  = poA;
    float lb  = 0.0f;
    if (b < 0.0f) {
        hb = fmaxf(hb, -C_LAM * b);
        if (fmaf(poA, C_INVLAM, b) < 0.0f) lb = poA;
    }
    t3 = fminf(fmaxf(t3, lb), hb);

    // ---- 4 Newton steps on F(t) = L^2 - R^2*nrm2 (sqrt-free, guard-free) ----
    #pragma unroll
    for (int k = 0; k < 4; k++) {
        float nrm2 = fmaf(t3, fmaf(t3, A, -2.0f * p), N);
        float L    = fmaf(-t3, A, p);
        float R    = fmaf(t3, C_INVLAM, b);
        float Rn   = R * nrm2;
        float s2   = fmaf(R, R, -A);
        float F    = fmaf(L, L, -R * Rn);
        float Fh   = fmaf(L, s2, -C_INVLAM * Rn);              // F'/2
        t3 = t3 - __fdividef(0.5f * F, Fh);
        t3 = fminf(fmaxf(t3, lb), hb);     // also recovers inf/nan steps
    }

    float nrm2 = fmaxf(fmaf(t3, fmaf(t3, A, -2.0f * p), N), C_EPS);
    float inv3 = fminf(rsqrtf(nrm2), 1.0f);                    // 1/max(nrm,1)
    float u3x  = fmaf(-t3, ax, ux) * inv3;
    float u3y  = fmaf(-t3, ay, uy) * inv3;

    float ox = feas1 ? u1x : (ok2 ? u2x : u3x);
    float oy = feas1 ? u1y : (ok2 ? u2y : u3y);
    return make_float2(ox, oy);
}

// 4 rows per thread: u = 2 x float4, obs = 6 x float4, out = 2 x float4.
// 4 independent Newton chains/thread hide div/FMA latency.
__global__ void __launch_bounds__(256, 5) cbf_fused4_kernel(
    const float4* __restrict__ u4,
    const float4* __restrict__ o4,
    float4*       __restrict__ out4,
    int nquad)
{
    int j = blockIdx.x * 256 + threadIdx.x;
    if (j >= nquad) return;

    float4 ua = u4[2 * j],     ub = u4[2 * j + 1];
    float4 c0 = o4[6 * j],     c1 = o4[6 * j + 1], c2 = o4[6 * j + 2];
    float4 c3 = o4[6 * j + 3], c4 = o4[6 * j + 4], c5 = o4[6 * j + 5];

    // row0: px,py = c0.z,c0.w ; vx,vy = c1.x,c1.y
    // row1: px,py = c2.x,c2.y ; vx,vy = c2.z,c2.w
    // row2: px,py = c3.z,c3.w ; vx,vy = c4.x,c4.y
    // row3: px,py = c5.x,c5.y ; vx,vy = c5.z,c5.w
    float2 r0 = solve_row(ua.x, ua.y, c0.z, c0.w, c1.x, c1.y);
    float2 r1 = solve_row(ua.z, ua.w, c2.x, c2.y, c2.z, c2.w);
    float2 r2 = solve_row(ub.x, ub.y, c3.z, c3.w, c4.x, c4.y);
    float2 r3 = solve_row(ub.z, ub.w, c5.x, c5.y, c5.z, c5.w);

    out4[2 * j]     = make_float4(r0.x, r0.y, r1.x, r1.y);
    out4[2 * j + 1] = make_float4(r2.x, r2.y, r3.x, r3.y);
}

// Scalar tail for n % 4 rows (not hit at B = 4M).
__global__ void cbf_tail_kernel(
    const float* __restrict__ u_nom,
    const float* __restrict__ obs,
    float*       __restrict__ out,
    int start, int n)
{
    int i = start + threadIdx.x;
    if (i >= n) return;
    const float* o = obs + 6 * i;
    float2 r = solve_row(u_nom[2 * i], u_nom[2 * i + 1], o[2], o[3], o[4], o[5]);
    out[2 * i]     = r.x;
    out[2 * i + 1] = r.y;
}

extern "C" void kernel_launch(void* const* d_in, const int* in_sizes, int n_in,
                              void* d_out, int out_size) {
    const float* u_nom = (const float*)d_in[0];
    const float* obs   = (const float*)d_in[1];
    float* out = (float*)d_out;

    int n = in_sizes[0] / 2;
    int nquad = n / 4;

    int threads = 256;
    int blocks  = (nquad + threads - 1) / threads;
    if (blocks > 0)
        cbf_fused4_kernel<<<blocks, threads>>>(
            (const float4*)u_nom, (const float4*)obs, (float4*)out, nquad);

    if (n & 3)
        cbf_tail_kernel<<<1, 4>>>(u_nom, obs, out, nquad * 4, n);
}